// round 17
// baseline (speedup 1.0000x reference)
#include <cuda_runtime.h>
#include <cuda_fp16.h>
#include <math.h>
#include <cstdint>

// Problem constants
#define BB 8
#define LL 1024
#define HH 8
#define EE 64
#define SS 1024
#define DD 64
#define BH (BB*HH)    // 64
#define NROWS (BH*LL) // 65536

// Static scratch (allocation-free rule: __device__ globals)
__device__ uint32_t g_QpH[(size_t)NROWS * 32];    // phi(Q) hi  fp16-pairs [row][kw]
__device__ uint32_t g_QpL[(size_t)NROWS * 32];    // phi(Q) lo
__device__ uint32_t g_KpH[(size_t)NROWS * 32];    // phi(K) hi
__device__ uint32_t g_KpL[(size_t)NROWS * 32];    // phi(K) lo
__device__ uint32_t g_VtH[(size_t)BH * DD * 512]; // V^T fp16 [bh][d][sw]
__device__ float    g_Sc[(size_t)BH * LL * SS];   // 256 MB raw scores (fp32)
__device__ float    g_s2[NROWS];
__device__ float    g_s4[NROWS];
__device__ int      g_mx[NROWS];

// ---------------------------------------------------------------------------
// Helpers
// ---------------------------------------------------------------------------
__device__ __forceinline__ void mma_f16(float* d, const uint32_t* a, const uint32_t* b) {
    asm volatile(
        "mma.sync.aligned.m16n8k16.row.col.f32.f16.f16.f32 "
        "{%0,%1,%2,%3}, {%4,%5,%6,%7}, {%8,%9}, {%0,%1,%2,%3};"
        : "+f"(d[0]), "+f"(d[1]), "+f"(d[2]), "+f"(d[3])
        : "r"(a[0]), "r"(a[1]), "r"(a[2]), "r"(a[3]), "r"(b[0]), "r"(b[1]));
}
__device__ __forceinline__ void ldm_x4(uint32_t* r, uint32_t a) {
    asm volatile("ldmatrix.sync.aligned.m8n8.x4.shared.b16 {%0,%1,%2,%3}, [%4];"
        : "=r"(r[0]), "=r"(r[1]), "=r"(r[2]), "=r"(r[3]) : "r"(a));
}
__device__ __forceinline__ uint32_t smem_u32(const void* p) {
    uint32_t a;
    asm("{ .reg .u64 t; cvta.to.shared.u64 t, %1; cvt.u32.u64 %0, t; }" : "=r"(a) : "l"(p));
    return a;
}
__device__ __forceinline__ void cp16(uint32_t sdst, const void* gsrc) {
    asm volatile("cp.async.cg.shared.global [%0], [%1], 16;" :: "r"(sdst), "l"(gsrc));
}
__device__ __forceinline__ void cp_commit() {
    asm volatile("cp.async.commit_group;" ::: "memory");
}
#define CP_WAIT(N) asm volatile("cp.async.wait_group %0;" :: "n"(N) : "memory")

__device__ __forceinline__ uint32_t packh2(__half a, __half b) {
    return (uint32_t)__half_as_ushort(a) | ((uint32_t)__half_as_ushort(b) << 16);
}
__device__ __forceinline__ float ex2f(float x) {
    float y;
    asm("ex2.approx.f32 %0, %1;" : "=f"(y) : "f"(x));
    return y;
}
#define LOG2E 1.4426950408889634f

// ---------------------------------------------------------------------------
// Phase A: phi_p for Q (y==0) and K (y==1); outputs fp16 hi/lo planes (both).
// ---------------------------------------------------------------------------
__global__ __launch_bounds__(256) void fa_phi_kernel(const float* __restrict__ qin,
                                                     const float* __restrict__ kin)
{
    int warp = blockIdx.x * 8 + (threadIdx.x >> 5);
    int lane = threadIdx.x & 31;
    int isK  = blockIdx.y;
    if (warp >= NROWS) return;

    int b = warp / (LL * HH);
    int l = (warp / HH) % LL;
    int h = warp % HH;

    const float2* src = (const float2*)((isK ? kin : qin) + (size_t)warp * EE);
    float2 xx = src[lane];
    float x0 = fmaxf(xx.x, 0.f), x1 = fmaxf(xx.y, 0.f);
    float a0 = x0 * x0, a1 = x1 * x1;
    float s2 = a0 + a1;
    float s4 = a0 * a0 + a1 * a1;
#pragma unroll
    for (int o = 16; o > 0; o >>= 1) {
        s2 += __shfl_xor_sync(0xffffffffu, s2, o);
        s4 += __shfl_xor_sync(0xffffffffu, s4, o);
    }
    float scale = (s4 > 0.f) ? sqrtf(s2) * rsqrtf(s4) : 0.f;

    float y0 = scale * a0, y1 = scale * a1;
    __half h0 = __float2half_rn(y0);
    __half h1 = __float2half_rn(y1);
    __half l0 = __float2half_rn(y0 - __half2float(h0));
    __half l1 = __float2half_rn(y1 - __half2float(h1));

    size_t row = (size_t)(b * HH + h) * LL + l;
    uint32_t* dH = (isK ? g_KpH : g_QpH) + row * 32;
    uint32_t* dL = (isK ? g_KpL : g_QpL) + row * 32;
    dH[lane] = packh2(h0, h1);
    dL[lane] = packh2(l0, l1);

    if (!isK && lane == 0) {
        g_s2[warp] = 0.f;
        g_s4[warp] = 0.f;
        g_mx[warp] = 0;
    }
}

// ---------------------------------------------------------------------------
// V transpose + fp16 pack: V[b][s][h][d] -> g_VtH[bh][d][s/2] packed pairs.
// ---------------------------------------------------------------------------
__global__ __launch_bounds__(256) void fa_vt_kernel(const float* __restrict__ V)
{
    __shared__ float sm[64][68];
    int bh = blockIdx.y;
    int b = bh >> 3, h = bh & 7;
    int s0 = blockIdx.x * 64;
    int tid = threadIdx.x;

#pragma unroll
    for (int i = 0; i < 4; i++) {
        int idx = tid + i * 256;
        int sl  = idx >> 4;
        int c4  = idx & 15;
        float4 v = *(const float4*)(V + (((size_t)b * SS + s0 + sl) * HH + h) * DD + c4 * 4);
        sm[c4*4+0][sl] = v.x; sm[c4*4+1][sl] = v.y;
        sm[c4*4+2][sl] = v.z; sm[c4*4+3][sl] = v.w;
    }
    __syncthreads();

    uint32_t* dst = g_VtH + (size_t)bh * DD * 512 + (s0 >> 1);
#pragma unroll
    for (int i = 0; i < 8; i++) {
        int idx = tid + i * 256;
        int d = idx >> 5;
        int w = idx & 31;
        dst[(size_t)d * 512 + w] = packh2(__float2half_rn(sm[d][2*w]),
                                          __float2half_rn(sm[d][2*w + 1]));
    }
}

// ---------------------------------------------------------------------------
// Phase B: QK via mma.sync fp16 3-pass hi/lo split (R14-proven), 4 N-tiles
// per CTA, double-buffered cp.async K tiles (hi+lo planes).
// ---------------------------------------------------------------------------
#define QKP 36    // words per fp16 row (32 data + 4 pad)
#define W_AL (128*QKP)
#define W_B0 (2*128*QKP)
#define W_BUF (2*128*QKP)
#define QK_SMEM ((2*128*QKP + 2*2*128*QKP) * 4)   // 110592

__global__ __launch_bounds__(256) void fa_qk_mma()
{
    extern __shared__ uint32_t sw[];
    uint32_t sb = smem_u32(sw);

    int bh = blockIdx.z;
    int m0 = blockIdx.y * 128;
    int nbase = blockIdx.x * 4;
    const uint32_t* qh = g_QpH + (size_t)bh * LL * 32;
    const uint32_t* ql = g_QpL + (size_t)bh * LL * 32;
    const uint32_t* kh = g_KpH + (size_t)bh * SS * 32;
    const uint32_t* kl = g_KpL + (size_t)bh * SS * 32;
    float* C = g_Sc + (size_t)bh * LL * SS;

    int tid = threadIdx.x, wid = tid >> 5, lane = tid & 31;
    int g = lane >> 2, tg = lane & 3;
    int wm = wid & 3, wn = wid >> 2;

    auto issueB = [&](int j, int buf) {
        if (j < 4) {
            int n0 = (nbase + j) * 128;
            uint32_t base = sb + (uint32_t)(W_B0 + buf * W_BUF) * 4;
#pragma unroll
            for (int i = 0; i < 4; i++) {
                int idx = tid + i * 256;
                int row = idx >> 3, seg = idx & 7;
                uint32_t so = (uint32_t)(row * QKP + seg * 4) * 4;
                cp16(base + so,                kh + (size_t)(n0 + row) * 32 + seg * 4);
                cp16(base + (128*QKP)*4 + so,  kl + (size_t)(n0 + row) * 32 + seg * 4);
            }
        }
        cp_commit();
    };

    {
#pragma unroll
        for (int i = 0; i < 4; i++) {
            int idx = tid + i * 256;
            int row = idx >> 3, seg = idx & 7;
            uint32_t so = (uint32_t)(row * QKP + seg * 4) * 4;
            cp16(sb + so,            qh + (size_t)(m0 + row) * 32 + seg * 4);
            cp16(sb + W_AL * 4 + so, ql + (size_t)(m0 + row) * 32 + seg * 4);
        }
        issueB(0, 0);
        issueB(1, 1);
    }

    int arow = wm * 32 + (lane & 15);
    uint32_t aoff = (uint32_t)(arow * QKP + ((lane >> 4) << 2)) * 4;
    int brow = wn * 64 + ((lane >> 4) << 3) + (lane & 7);
    uint32_t boff = (uint32_t)(brow * QKP + (((lane >> 3) & 1) << 2)) * 4;
    uint32_t aAH = sb, aAL = sb + W_AL * 4;

    float st2[2][2] = {{0,0},{0,0}};
    float st4[2][2] = {{0,0},{0,0}};
    float stm[2][2] = {{0,0},{0,0}};

    for (int j = 0; j < 4; j++) {
        CP_WAIT(1);
        __syncthreads();
        int buf = j & 1;
        uint32_t aBH = sb + (uint32_t)(W_B0 + buf * W_BUF) * 4;
        uint32_t aBL = aBH + (128*QKP)*4;

        float acc[2][8][4];
#pragma unroll
        for (int mt = 0; mt < 2; mt++)
#pragma unroll
            for (int nt = 0; nt < 8; nt++)
#pragma unroll
                for (int q = 0; q < 4; q++) acc[mt][nt][q] = 0.f;

#pragma unroll
        for (int ks = 0; ks < 4; ks++) {
            uint32_t kb = ks * 32;
            uint32_t ahi0[4], ahi1[4], alo0[4], alo1[4];
            ldm_x4(ahi0, aAH + aoff + kb);
            ldm_x4(ahi1, aAH + aoff + kb + 16 * QKP * 4);
            ldm_x4(alo0, aAL + aoff + kb);
            ldm_x4(alo1, aAL + aoff + kb + 16 * QKP * 4);
#pragma unroll
            for (int p = 0; p < 4; p++) {
                uint32_t bh4[4], bl4[4];
                uint32_t bo = boff + kb + p * 16 * QKP * 4;
                ldm_x4(bh4, aBH + bo);
                ldm_x4(bl4, aBL + bo);
#pragma unroll
                for (int q = 0; q < 2; q++) {
                    int nt = p * 2 + q;
                    mma_f16(acc[0][nt], ahi0, &bh4[q*2]);
                    mma_f16(acc[0][nt], ahi0, &bl4[q*2]);
                    mma_f16(acc[0][nt], alo0, &bh4[q*2]);
                    mma_f16(acc[1][nt], ahi1, &bh4[q*2]);
                    mma_f16(acc[1][nt], ahi1, &bl4[q*2]);
                    mma_f16(acc[1][nt], alo1, &bh4[q*2]);
                }
            }
        }
        __syncthreads();
        issueB(j + 2, buf);

        int n0 = (nbase + j) * 128;
#pragma unroll
        for (int mt = 0; mt < 2; mt++) {
            int r0 = wm * 32 + mt * 16 + g;
            int r1 = r0 + 8;
#pragma unroll
            for (int nt = 0; nt < 8; nt++) {
                float* cc = acc[mt][nt];
                float q0 = cc[0]*cc[0]; st2[mt][0] += q0; st4[mt][0] += q0*q0; stm[mt][0] = fmaxf(stm[mt][0], q0);
                float q1 = cc[1]*cc[1]; st2[mt][0] += q1; st4[mt][0] += q1*q1; stm[mt][0] = fmaxf(stm[mt][0], q1);
                float q2 = cc[2]*cc[2]; st2[mt][1] += q2; st4[mt][1] += q2*q2; stm[mt][1] = fmaxf(stm[mt][1], q2);
                float q3 = cc[3]*cc[3]; st2[mt][1] += q3; st4[mt][1] += q3*q3; stm[mt][1] = fmaxf(stm[mt][1], q3);
                int col = n0 + wn * 64 + nt * 8 + tg * 2;
                *(float2*)(C + (size_t)(m0 + r0) * SS + col) = make_float2(cc[0], cc[1]);
                *(float2*)(C + (size_t)(m0 + r1) * SS + col) = make_float2(cc[2], cc[3]);
            }
        }
    }

#pragma unroll
    for (int mt = 0; mt < 2; mt++) {
        float s2a = st2[mt][0], s4a = st4[mt][0], mxa = stm[mt][0];
        float s2b = st2[mt][1], s4b = st4[mt][1], mxb = stm[mt][1];
#pragma unroll
        for (int o = 1; o <= 2; o <<= 1) {
            s2a += __shfl_xor_sync(0xffffffffu, s2a, o);
            s4a += __shfl_xor_sync(0xffffffffu, s4a, o);
            mxa  = fmaxf(mxa, __shfl_xor_sync(0xffffffffu, mxa, o));
            s2b += __shfl_xor_sync(0xffffffffu, s2b, o);
            s4b += __shfl_xor_sync(0xffffffffu, s4b, o);
            mxb  = fmaxf(mxb, __shfl_xor_sync(0xffffffffu, mxb, o));
        }
        if (tg == 0) {
            int ga = bh * LL + m0 + wm * 32 + mt * 16 + g;
            atomicAdd(&g_s2[ga], s2a);
            atomicAdd(&g_s4[ga], s4a);
            atomicMax(&g_mx[ga], __float_as_int(mxa));
            int gb = ga + 8;
            atomicAdd(&g_s2[gb], s2b);
            atomicAdd(&g_s4[gb], s4b);
            atomicMax(&g_mx[gb], __float_as_int(mxb));
        }
    }
}

// ---------------------------------------------------------------------------
// Phase C: AV, register-resident A fragments; 16-column chunks, 4-slot ring
// (61.4 KB smem -> 3 CTAs/SM). 8 warps as 8M x 1N; 64 chunks over S=1024.
// ---------------------------------------------------------------------------
#define AVW 24                      // A stage row stride (floats; 16 data + 8 pad)
#define BVW 12                      // V slot row stride (words; 8 data + 4 pad)
#define A_SLOT (128 * AVW * 4)      // 12288
#define B_SLOT (64 * BVW * 4)       // 3072
#define OF_A 0                      // 4 slots: 49152
#define OF_B 49152                  // 4 slots: 12288 -> 61440
#define AV_SMEM 61440

__global__ __launch_bounds__(256) void fa_av_mma(float* __restrict__ out)
{
    extern __shared__ char smc[];
    uint32_t sb = smem_u32(smc);

    int bh = blockIdx.y;
    int b = bh >> 3, h = bh & 7;
    int m0 = blockIdx.x * 128;
    const float* A = g_Sc + (size_t)bh * LL * SS;
    const uint32_t* Vt = g_VtH + (size_t)bh * DD * 512;

    int tid = threadIdx.x, wid = tid >> 5, lane = tid & 31;
    int g = lane >> 2, tg = lane & 3;

    auto issue = [&](int ch, int slot) {
        if (ch < 64) {
#pragma unroll
            for (int i = 0; i < 2; i++) {
                int idx = tid + i * 256;      // 0..511 = 128 rows x 4 segs
                int row = idx >> 2, seg = idx & 3;
                cp16(sb + OF_A + slot * A_SLOT + (uint32_t)(row * AVW + seg * 4) * 4,
                     A + (size_t)(m0 + row) * SS + ch * 16 + seg * 4);
            }
            if (tid < 128) {                  // 64 d-rows x 2 segs
                int d = tid >> 1, seg = tid & 1;
                cp16(sb + OF_B + slot * B_SLOT + (uint32_t)(d * BVW + seg * 4) * 4,
                     Vt + (size_t)d * 512 + ch * 8 + seg * 4);
            }
        }
        cp_commit();
    };

    issue(0, 0);
    issue(1, 1);
    issue(2, 2);

    // warp-owned rows
    int r0 = wid * 16 + g;
    int r1 = r0 + 8;
    int gr0 = bh * LL + m0 + r0;
    int gr1 = gr0 + 8;
    float s2a = g_s2[gr0], s4a = g_s4[gr0];
    float s2b = g_s2[gr1], s4b = g_s4[gr1];
    float c0 = ((s4a > 0.f) ? sqrtf(s2a) * rsqrtf(s4a) : 0.f) * LOG2E;
    float c1 = ((s4b > 0.f) ? sqrtf(s2b) * rsqrtf(s4b) : 0.f) * LOG2E;
    float mm0 = c0 * __int_as_float(g_mx[gr0]);
    float mm1 = c1 * __int_as_float(g_mx[gr1]);
    float rs0 = 0.f, rs1 = 0.f;

    // V ldmatrix byte offsets, one per 16-d block p
    uint32_t bofs[4];
#pragma unroll
    for (int p = 0; p < 4; p++) {
        int brow = p * 16 + ((lane >> 4) << 3) + (lane & 7);
        bofs[p] = (uint32_t)(brow * BVW + (((lane >> 3) & 1) << 2)) * 4;
    }

    float acc[8][4];
#pragma unroll
    for (int nt = 0; nt < 8; nt++)
#pragma unroll
        for (int q = 0; q < 4; q++) acc[nt][q] = 0.f;

    for (int ch = 0; ch < 64; ch++) {
        int slot = ch & 3;
        CP_WAIT(2);
        __syncthreads();                 // chunk ch staged; chunk ch-1 consumed by all
        issue(ch + 3, (ch + 3) & 3);     // refill the slot freed last iteration

        const float* base = (const float*)(smc + OF_A + slot * A_SLOT);
        uint32_t bbase = sb + OF_B + slot * B_SLOT;

        // A fragments: LDS fp32 pairs -> exp2 -> fp16 pack in registers
        const float* p0 = base + r0 * AVW + 2 * tg;
        const float* p1 = base + r1 * AVW + 2 * tg;
        float2 v00 = *(const float2*)p0;
        float2 v01 = *(const float2*)(p0 + 8);
        float2 v10 = *(const float2*)p1;
        float2 v11 = *(const float2*)(p1 + 8);
        __half e00 = __float2half_rn(ex2f(fmaf(c0 * v00.x, v00.x, -mm0)));
        __half e01 = __float2half_rn(ex2f(fmaf(c0 * v00.y, v00.y, -mm0)));
        __half e02 = __float2half_rn(ex2f(fmaf(c0 * v01.x, v01.x, -mm0)));
        __half e03 = __float2half_rn(ex2f(fmaf(c0 * v01.y, v01.y, -mm0)));
        __half e10 = __float2half_rn(ex2f(fmaf(c1 * v10.x, v10.x, -mm1)));
        __half e11 = __float2half_rn(ex2f(fmaf(c1 * v10.y, v10.y, -mm1)));
        __half e12 = __float2half_rn(ex2f(fmaf(c1 * v11.x, v11.x, -mm1)));
        __half e13 = __float2half_rn(ex2f(fmaf(c1 * v11.y, v11.y, -mm1)));
        rs0 += (__half2float(e00) + __half2float(e01))
             + (__half2float(e02) + __half2float(e03));
        rs1 += (__half2float(e10) + __half2float(e11))
             + (__half2float(e12) + __half2float(e13));
        uint32_t a[4];
        a[0] = packh2(e00, e01);      // row r0, k = 2tg..2tg+1
        a[1] = packh2(e10, e11);      // row r1
        a[2] = packh2(e02, e03);      // row r0, k+8
        a[3] = packh2(e12, e13);      // row r1, k+8

#pragma unroll
        for (int p = 0; p < 4; p++) {
            uint32_t b4[4];
            ldm_x4(b4, bbase + bofs[p]);
            mma_f16(acc[p*2],     a, &b4[0]);
            mma_f16(acc[p*2 + 1], a, &b4[2]);
        }
        // single sync per chunk: next iteration's top sync orders slot reuse
    }

    // Row sums: butterfly over the 4 tg lanes (rows are warp-exclusive)
    rs0 += __shfl_xor_sync(0xffffffffu, rs0, 1);
    rs0 += __shfl_xor_sync(0xffffffffu, rs0, 2);
    rs1 += __shfl_xor_sync(0xffffffffu, rs1, 1);
    rs1 += __shfl_xor_sync(0xffffffffu, rs1, 2);
    float i0 = 1.f / rs0;
    float i1 = 1.f / rs1;

    // Normalize + scatter to out[b][l][h][d]
    float* o0 = out + (((size_t)b * LL + m0 + r0) * HH + h) * DD;
    float* o1 = out + (((size_t)b * LL + m0 + r1) * HH + h) * DD;
#pragma unroll
    for (int nt = 0; nt < 8; nt++) {
        int col = nt * 8 + tg * 2;
        *(float2*)(o0 + col) = make_float2(acc[nt][0] * i0, acc[nt][1] * i0);
        *(float2*)(o1 + col) = make_float2(acc[nt][2] * i1, acc[nt][3] * i1);
    }
}

// ---------------------------------------------------------------------------
extern "C" void kernel_launch(void* const* d_in, const int* in_sizes, int n_in,
                              void* d_out, int out_size)
{
    const float* q = (const float*)d_in[0];   // [B,L,H,E]
    const float* k = (const float*)d_in[1];   // [B,S,H,E]
    const float* v = (const float*)d_in[2];   // [B,S,H,D]
    float* out = (float*)d_out;               // [B,L,H,D]

    cudaFuncSetAttribute(fa_qk_mma, cudaFuncAttributeMaxDynamicSharedMemorySize, QK_SMEM);
    cudaFuncSetAttribute(fa_av_mma, cudaFuncAttributeMaxDynamicSharedMemorySize, AV_SMEM);
    cudaFuncSetAttribute(fa_qk_mma, cudaFuncAttributePreferredSharedMemoryCarveout, 100);
    cudaFuncSetAttribute(fa_av_mma, cudaFuncAttributePreferredSharedMemoryCarveout, 100);

    fa_phi_kernel<<<dim3(8192, 2), 256>>>(q, k);
    fa_vt_kernel<<<dim3(16, BH), 256>>>(v);
    fa_qk_mma<<<dim3(2, 8, BH), 256, QK_SMEM>>>();
    fa_av_mma<<<dim3(8, BH), 256, AV_SMEM>>>(out);
}